// round 1
// baseline (speedup 1.0000x reference)
#include <cuda_runtime.h>
#include <math.h>

// Problem constants
#define B_  16
#define T_  32
#define C_  64
#define H_  32
#define W_  32
#define CHW   (C_ * H_ * W_)       // 65536
#define CHW4  (CHW / 4)            // 16384 float4 per (b,t) slice
#define NVEC  (B_ * CHW4)          // 262144 thread work items

#define VTH_M   0.5f
#define VTH_S   0.1f
#define DECAY_M 2.0f
#define DECAY_S 0.1f

__device__ __forceinline__ float softplus_acc(float z) {
    // numerically-stable softplus matching jax.nn.softplus
    // softplus(z) = log1p(exp(z)) for z small, ~z for large z
    if (z > 20.0f) return z;
    return log1pf(expf(z));
}

__device__ __forceinline__ float sigmoid_acc(float z) {
    return 1.0f / (1.0f + expf(-z));
}

__global__ void __launch_bounds__(256) hlif_kernel(
    const float4* __restrict__ x,
    const float*  __restrict__ vth_raw,
    const float*  __restrict__ decay_raw,
    float4*       __restrict__ out)
{
    int idx = blockIdx.x * blockDim.x + threadIdx.x;   // 0 .. NVEC-1
    int p = idx & (CHW4 - 1);       // vec index within (C,H,W)
    int b = idx >> 14;              // batch index (CHW4 = 2^14)

    // per-neuron params (4 neurons per thread)
    float4 vr = reinterpret_cast<const float4*>(vth_raw)[p];
    float4 dr = reinterpret_cast<const float4*>(decay_raw)[p];

    float4 vth, dec;
    vth.x = softplus_acc(fmaf(vr.x, VTH_S, VTH_M)) + 0.01f;
    vth.y = softplus_acc(fmaf(vr.y, VTH_S, VTH_M)) + 0.01f;
    vth.z = softplus_acc(fmaf(vr.z, VTH_S, VTH_M)) + 0.01f;
    vth.w = softplus_acc(fmaf(vr.w, VTH_S, VTH_M)) + 0.01f;
    dec.x = fminf(fmaxf(sigmoid_acc(fmaf(dr.x, DECAY_S, DECAY_M)), 0.0f), 0.99f);
    dec.y = fminf(fmaxf(sigmoid_acc(fmaf(dr.y, DECAY_S, DECAY_M)), 0.0f), 0.99f);
    dec.z = fminf(fmaxf(sigmoid_acc(fmaf(dr.z, DECAY_S, DECAY_M)), 0.0f), 0.99f);
    dec.w = fminf(fmaxf(sigmoid_acc(fmaf(dr.w, DECAY_S, DECAY_M)), 0.0f), 0.99f);

    const float4* xb = x   + (size_t)b * (T_ * CHW4) + p;
    float4*       ob = out + (size_t)b * (T_ * CHW4) + p;

    float4 v = make_float4(0.0f, 0.0f, 0.0f, 0.0f);

    #pragma unroll
    for (int t = 0; t < T_; ++t) {
        float4 xt = xb[(size_t)t * CHW4];

        float4 s;
        v.x = fmaf(v.x, dec.x, xt.x);
        v.y = fmaf(v.y, dec.y, xt.y);
        v.z = fmaf(v.z, dec.z, xt.z);
        v.w = fmaf(v.w, dec.w, xt.w);

        s.x = (v.x - vth.x > 0.0f) ? 1.0f : 0.0f;
        s.y = (v.y - vth.y > 0.0f) ? 1.0f : 0.0f;
        s.z = (v.z - vth.z > 0.0f) ? 1.0f : 0.0f;
        s.w = (v.w - vth.w > 0.0f) ? 1.0f : 0.0f;

        v.x -= s.x * vth.x;
        v.y -= s.y * vth.y;
        v.z -= s.z * vth.z;
        v.w -= s.w * vth.w;

        ob[(size_t)t * CHW4] = s;
    }
}

extern "C" void kernel_launch(void* const* d_in, const int* in_sizes, int n_in,
                              void* d_out, int out_size)
{
    const float4* x         = (const float4*)d_in[0];
    const float*  vth_raw   = (const float*)d_in[1];
    const float*  decay_raw = (const float*)d_in[2];
    float4* out = (float4*)d_out;

    const int threads = 256;
    const int blocks  = NVEC / threads;   // 1024
    hlif_kernel<<<blocks, threads>>>(x, vth_raw, decay_raw, out);
}

// round 2
// speedup vs baseline: 1.0447x; 1.0447x over previous
#include <cuda_runtime.h>
#include <math.h>

// Problem constants
#define B_  16
#define T_  32
#define C_  64
#define H_  32
#define W_  32
#define CHW   (C_ * H_ * W_)       // 65536
#define CHW4  (CHW / 4)            // 16384 float4 per (b,t) slice
#define NVEC  (B_ * CHW4)          // 262144 thread work items

#define VTH_M   0.5f
#define VTH_S   0.1f
#define DECAY_M 2.0f
#define DECAY_S 0.1f

#define PF 4   // prefetch pipeline depth

__device__ __forceinline__ float softplus_acc(float z) {
    if (z > 20.0f) return z;
    return log1pf(expf(z));
}

__device__ __forceinline__ float sigmoid_acc(float z) {
    return 1.0f / (1.0f + expf(-z));
}

__global__ void __launch_bounds__(256) hlif_kernel(
    const float4* __restrict__ x,
    const float*  __restrict__ vth_raw,
    const float*  __restrict__ decay_raw,
    float4*       __restrict__ out)
{
    int idx = blockIdx.x * blockDim.x + threadIdx.x;   // 0 .. NVEC-1
    int p = idx & (CHW4 - 1);       // vec index within (C,H,W)
    int b = idx >> 14;              // batch index (CHW4 = 2^14)

    const float4* xb = x   + (size_t)b * (T_ * CHW4) + p;
    float4*       ob = out + (size_t)b * (T_ * CHW4) + p;

    // Kick off the prefetch pipeline FIRST so the param math (MUFU-heavy)
    // overlaps with the first DRAM loads.
    float4 buf[PF];
    #pragma unroll
    for (int i = 0; i < PF; ++i)
        buf[i] = __ldcs(xb + (size_t)i * CHW4);

    // per-neuron params (4 neurons per thread)
    float4 vr = reinterpret_cast<const float4*>(vth_raw)[p];
    float4 dr = reinterpret_cast<const float4*>(decay_raw)[p];

    float4 vth, dec;
    vth.x = softplus_acc(fmaf(vr.x, VTH_S, VTH_M)) + 0.01f;
    vth.y = softplus_acc(fmaf(vr.y, VTH_S, VTH_M)) + 0.01f;
    vth.z = softplus_acc(fmaf(vr.z, VTH_S, VTH_M)) + 0.01f;
    vth.w = softplus_acc(fmaf(vr.w, VTH_S, VTH_M)) + 0.01f;
    dec.x = fminf(fmaxf(sigmoid_acc(fmaf(dr.x, DECAY_S, DECAY_M)), 0.0f), 0.99f);
    dec.y = fminf(fmaxf(sigmoid_acc(fmaf(dr.y, DECAY_S, DECAY_M)), 0.0f), 0.99f);
    dec.z = fminf(fmaxf(sigmoid_acc(fmaf(dr.z, DECAY_S, DECAY_M)), 0.0f), 0.99f);
    dec.w = fminf(fmaxf(sigmoid_acc(fmaf(dr.w, DECAY_S, DECAY_M)), 0.0f), 0.99f);

    float4 v = make_float4(0.0f, 0.0f, 0.0f, 0.0f);

    #pragma unroll
    for (int t = 0; t < T_; ++t) {
        float4 xt = buf[t & (PF - 1)];
        // prefetch t+PF before the dependent compute of t
        if (t + PF < T_)
            buf[t & (PF - 1)] = __ldcs(xb + (size_t)(t + PF) * CHW4);

        float4 s;
        v.x = fmaf(v.x, dec.x, xt.x);
        v.y = fmaf(v.y, dec.y, xt.y);
        v.z = fmaf(v.z, dec.z, xt.z);
        v.w = fmaf(v.w, dec.w, xt.w);

        s.x = (v.x - vth.x > 0.0f) ? 1.0f : 0.0f;
        s.y = (v.y - vth.y > 0.0f) ? 1.0f : 0.0f;
        s.z = (v.z - vth.z > 0.0f) ? 1.0f : 0.0f;
        s.w = (v.w - vth.w > 0.0f) ? 1.0f : 0.0f;

        v.x -= s.x * vth.x;
        v.y -= s.y * vth.y;
        v.z -= s.z * vth.z;
        v.w -= s.w * vth.w;

        __stcs(ob + (size_t)t * CHW4, s);
    }
}

extern "C" void kernel_launch(void* const* d_in, const int* in_sizes, int n_in,
                              void* d_out, int out_size)
{
    const float4* x         = (const float4*)d_in[0];
    const float*  vth_raw   = (const float*)d_in[1];
    const float*  decay_raw = (const float*)d_in[2];
    float4* out = (float4*)d_out;

    const int threads = 256;
    const int blocks  = NVEC / threads;   // 1024
    hlif_kernel<<<blocks, threads>>>(x, vth_raw, decay_raw, out);
}

// round 3
// speedup vs baseline: 1.0476x; 1.0028x over previous
#include <cuda_runtime.h>
#include <math.h>

// Problem constants
#define B_  16
#define T_  32
#define C_  64
#define H_  32
#define W_  32
#define CHW   (C_ * H_ * W_)       // 65536
#define CHW4  (CHW / 4)            // 16384 float4 per (b,t) slice
#define NVEC  (B_ * CHW4)          // 262144 thread work items

#define VTH_M   0.5f
#define VTH_S   0.1f
#define DECAY_M 2.0f
#define DECAY_S 0.1f

#define PF 8   // prefetch pipeline depth (ring of float4 = 32 regs)

__device__ __forceinline__ float softplus_acc(float z) {
    if (z > 20.0f) return z;
    return log1pf(expf(z));
}

__device__ __forceinline__ float sigmoid_acc(float z) {
    return 1.0f / (1.0f + expf(-z));
}

__global__ void __launch_bounds__(256) hlif_kernel(
    const float4* __restrict__ x,
    const float*  __restrict__ vth_raw,
    const float*  __restrict__ decay_raw,
    float4*       __restrict__ out)
{
    int idx = blockIdx.x * blockDim.x + threadIdx.x;   // 0 .. NVEC-1
    int p = idx & (CHW4 - 1);       // vec index within (C,H,W)
    int b = idx >> 14;              // batch index (CHW4 = 2^14)

    const float4* xb = x   + (size_t)b * (T_ * CHW4) + p;
    float4*       ob = out + (size_t)b * (T_ * CHW4) + p;

    // Kick off a deep prefetch pipeline FIRST so the param math (MUFU-heavy)
    // overlaps with the first 8 DRAM loads in flight.
    float4 buf[PF];
    #pragma unroll
    for (int i = 0; i < PF; ++i)
        buf[i] = __ldcs(xb + (size_t)i * CHW4);

    // per-neuron params (4 neurons per thread)
    float4 vr = reinterpret_cast<const float4*>(vth_raw)[p];
    float4 dr = reinterpret_cast<const float4*>(decay_raw)[p];

    float4 vth, dec;
    vth.x = softplus_acc(fmaf(vr.x, VTH_S, VTH_M)) + 0.01f;
    vth.y = softplus_acc(fmaf(vr.y, VTH_S, VTH_M)) + 0.01f;
    vth.z = softplus_acc(fmaf(vr.z, VTH_S, VTH_M)) + 0.01f;
    vth.w = softplus_acc(fmaf(vr.w, VTH_S, VTH_M)) + 0.01f;
    dec.x = fminf(fmaxf(sigmoid_acc(fmaf(dr.x, DECAY_S, DECAY_M)), 0.0f), 0.99f);
    dec.y = fminf(fmaxf(sigmoid_acc(fmaf(dr.y, DECAY_S, DECAY_M)), 0.0f), 0.99f);
    dec.z = fminf(fmaxf(sigmoid_acc(fmaf(dr.z, DECAY_S, DECAY_M)), 0.0f), 0.99f);
    dec.w = fminf(fmaxf(sigmoid_acc(fmaf(dr.w, DECAY_S, DECAY_M)), 0.0f), 0.99f);

    float4 v = make_float4(0.0f, 0.0f, 0.0f, 0.0f);

    #pragma unroll
    for (int t = 0; t < T_; ++t) {
        float4 xt = buf[t & (PF - 1)];
        // refill slot with t+PF before the dependent compute of t
        if (t + PF < T_)
            buf[t & (PF - 1)] = __ldcs(xb + (size_t)(t + PF) * CHW4);

        float4 s;
        v.x = fmaf(v.x, dec.x, xt.x);
        v.y = fmaf(v.y, dec.y, xt.y);
        v.z = fmaf(v.z, dec.z, xt.z);
        v.w = fmaf(v.w, dec.w, xt.w);

        s.x = (v.x - vth.x > 0.0f) ? 1.0f : 0.0f;
        s.y = (v.y - vth.y > 0.0f) ? 1.0f : 0.0f;
        s.z = (v.z - vth.z > 0.0f) ? 1.0f : 0.0f;
        s.w = (v.w - vth.w > 0.0f) ? 1.0f : 0.0f;

        v.x -= s.x * vth.x;
        v.y -= s.y * vth.y;
        v.z -= s.z * vth.z;
        v.w -= s.w * vth.w;

        __stcs(ob + (size_t)t * CHW4, s);
    }
}

extern "C" void kernel_launch(void* const* d_in, const int* in_sizes, int n_in,
                              void* d_out, int out_size)
{
    const float4* x         = (const float4*)d_in[0];
    const float*  vth_raw   = (const float*)d_in[1];
    const float*  decay_raw = (const float*)d_in[2];
    float4* out = (float4*)d_out;

    const int threads = 256;
    const int blocks  = NVEC / threads;   // 1024
    hlif_kernel<<<blocks, threads>>>(x, vth_raw, decay_raw, out);
}